// round 11
// baseline (speedup 1.0000x reference)
#include <cuda_runtime.h>
#include <cuda_fp16.h>
#include <cstdint>

// ---------------------------------------------------------------------------
// GlobalPropagation: 3-hop symmetric-normalized graph propagation (GCN-style)
//   H^{k+1}[i] = sum_{e: row_e==i} dinv_i*dinv_j*H^k[j]  (+ self loop)
//
// Scaled-H formulation: store Hs = dinv .* H. Then
//   S[r]   = sum_{(r,c)} Hs[c] + Hs[r]
//   H'[r]  = dinv_r * S[r]          (final hop, f32 out)
//   Hs'[r] = dinv_r^2 * S[r]        (intermediate hops, fp16)
// => CSR needs ONLY col indices (4 B/edge), no per-edge weight.
//
// Hops sit at the L2 bandwidth roofline (fp16 storage, fp32 accum,
// ~859 MB/hop @ ~11.2 TB/s). Build path compressed to 4 launches:
// deg_init -> hist -> single-pass scan (+ concurrent cvt blocks) -> fill.
// ---------------------------------------------------------------------------

#define FEAT 128                 // feature dim
#define N_MAX 131072             // >= 100000 nodes
#define E_MAX 3400000            // >= 3200000 edges
#define CSR_MAX (E_MAX + N_MAX)  // edges + self loops
#define SCAN_B 1024

// Scratch (allocation-free rule: __device__ globals)
__device__ int   g_is64;
__device__ int   g_deg[N_MAX];
__device__ int   g_off[N_MAX + 1];
__device__ int   g_cur[N_MAX];
__device__ float g_dinv[N_MAX];
__device__ int   g_col[CSR_MAX];       // col-only CSR (4 B/edge)
__device__ int   g_bsum[(N_MAX + SCAN_B - 1) / SCAN_B];  // block totals; 0 = not ready
__device__ __half g_bufA[(size_t)N_MAX * FEAT];
__device__ __half g_bufB[(size_t)N_MAX * FEAT];

// ---------------------------------------------------------------------------
// 1) degree init (self loop contributes 1) + bsum/flag reset + dtype sniff.
//    int64 little-endian view of small values is [val,0,val,0,...], so
//    "odd int32 words of first 8 elements all zero" <=> int64.
__global__ void k_deg_init(const unsigned int* __restrict__ p, int n, int nscan) {
    int i = blockIdx.x * blockDim.x + threadIdx.x;
    if (i < n) g_deg[i] = 1;
    if (i < nscan) g_bsum[i] = 0;       // doubles as ready-flag (totals >= 1)
    if (i == 0) {
        bool is64 = true;
        #pragma unroll
        for (int k = 1; k < 16; k += 2) is64 = is64 && (p[k] == 0u);
        g_is64 = is64 ? 1 : 0;
    }
}

// 2) histogram of row indices (rows = elements [0, e)), 2 edges per thread
__global__ void k_deg_hist(const void* __restrict__ edges, int e) {
    int i = blockIdx.x * blockDim.x + threadIdx.x;
    int base = i * 2;
    if (base >= e) return;
    if (g_is64) {
        const long long* p = (const long long*)edges;
        if (base + 1 < e) {
            longlong2 v = ((const longlong2*)p)[i];
            atomicAdd(&g_deg[(int)v.x], 1);
            atomicAdd(&g_deg[(int)v.y], 1);
        } else {
            atomicAdd(&g_deg[(int)p[base]], 1);
        }
    } else {
        const int* p = (const int*)edges;
        if (base + 1 < e) {
            int2 v = ((const int2*)p)[i];
            atomicAdd(&g_deg[v.x], 1);
            atomicAdd(&g_deg[v.y], 1);
        } else {
            atomicAdd(&g_deg[p[base]], 1);
        }
    }
}

// 3) Single-pass scan + concurrent cvt.
//    Blocks [0, nscan): block-local exclusive scan of g_deg; publish block
//    total to g_bsum[b] (its own ready flag, value >= 1); warp 0 spin-sums all
//    predecessor totals (independent publishes -> no serial chain); then write
//    g_off/g_cur/g_dinv and the tail sentinel.
//    Blocks [nscan, ...): cvt quads Hs0 = dinv .* H (dinv recomputed from
//    g_deg locally -- no dependency on the scan result).
//    Deadlock-free: scan blocks only wait on other scan blocks; cvt blocks
//    always drain and free SMs.
__global__ void __launch_bounds__(SCAN_B)
k_scan(const float* __restrict__ hin, int n, int total, int nscan, int total4) {
    int b = blockIdx.x;
    if (b < nscan) {
        __shared__ int sh[SCAN_B];
        __shared__ int base_sh;
        int i = b * SCAN_B + threadIdx.x;
        int v = (i < n) ? g_deg[i] : 0;
        sh[threadIdx.x] = v;
        __syncthreads();
        #pragma unroll
        for (int off = 1; off < SCAN_B; off <<= 1) {
            int t = (threadIdx.x >= off) ? sh[threadIdx.x - off] : 0;
            __syncthreads();
            sh[threadIdx.x] += t;
            __syncthreads();
        }
        int local_excl = sh[threadIdx.x] - v;
        // publish our block total (acts as its own ready flag; >= 1 always)
        if (threadIdx.x == SCAN_B - 1)
            atomicExch(&g_bsum[b], sh[SCAN_B - 1]);
        // warp 0: sum predecessor totals (spin until each is published)
        if (threadIdx.x < 32) {
            int acc = 0;
            for (int k = threadIdx.x; k < b; k += 32) {
                int s;
                do { s = atomicAdd(&g_bsum[k], 0); } while (s == 0);
                acc += s;
            }
            #pragma unroll
            for (int off = 16; off > 0; off >>= 1)
                acc += __shfl_down_sync(0xffffffffu, acc, off);
            if (threadIdx.x == 0) base_sh = acc;
        }
        __syncthreads();
        if (i < n) {
            int o = local_excl + base_sh;
            g_off[i] = o;
            g_cur[i] = o;
            g_dinv[i] = rsqrtf((float)g_deg[i]);
        }
        if (i == 0) g_off[n] = total;
    } else {
        // cvt: one float4 -> 4 scaled fp16 per thread
        int q = (b - nscan) * SCAN_B + threadIdx.x;
        if (q < total4) {
            int node = q >> 5;               // FEAT/4 = 32 quads per node
            float d = rsqrtf((float)g_deg[node]);
            float4 v = ((const float4*)hin)[q];
            __half2 a = __floats2half2_rn(v.x * d, v.y * d);
            __half2 bb = __floats2half2_rn(v.z * d, v.w * d);
            uint2 o;
            o.x = *reinterpret_cast<unsigned int*>(&a);
            o.y = *reinterpret_cast<unsigned int*>(&bb);
            ((uint2*)g_bufA)[q] = o;
        }
    }
}

// 4) fill (col-only CSR, 2 edges/thread) + self loops.
__global__ void k_fill(const void* __restrict__ edges, int e, int n) {
    int i = blockIdx.x * blockDim.x + threadIdx.x;
    int eh = (e + 1) >> 1;
    if (i < eh) {
        int r0, c0, r1 = -1, c1 = 0;
        int base = i * 2;
        if (g_is64) {
            const long long* p = (const long long*)edges;
            if (base + 1 < e) {
                longlong2 rv = ((const longlong2*)p)[i];
                longlong2 cv = ((const longlong2*)(p + e))[i];
                r0 = (int)rv.x; r1 = (int)rv.y;
                c0 = (int)cv.x; c1 = (int)cv.y;
            } else {
                r0 = (int)p[base]; c0 = (int)p[e + base];
            }
        } else {
            const int* p = (const int*)edges;
            if (base + 1 < e) {
                int2 rv = ((const int2*)p)[i];
                int2 cv = ((const int2*)(p + e))[i];
                r0 = rv.x; r1 = rv.y;
                c0 = cv.x; c1 = cv.y;
            } else {
                r0 = p[base]; c0 = p[e + base];
            }
        }
        g_col[atomicAdd(&g_cur[r0], 1)] = c0;
        if (r1 >= 0) g_col[atomicAdd(&g_cur[r1], 1)] = c1;
    } else if (i < eh + n) {
        int r = i - eh;                  // self loop
        g_col[atomicAdd(&g_cur[r], 1)] = r;
    }
}

// 5) warp-per-row gather SpMM over fp16 scaled rows, fp32 accumulation.
//    Lane l covers features [4l,4l+4): one uint2 (4 x fp16) per neighbor.
//    Epilogue applies dinv_r (final f32 out) or dinv_r^2 (fp16 intermediate).
//    SRC: 1 = g_bufA, 2 = g_bufB.  DST: 0 = f32 external out, 1/2 = fp16 bufs.
template <int SRC, int DST>
__global__ void __launch_bounds__(256)
k_spmm(float* __restrict__ Oext, int n) {
    const __half* __restrict__ Hin = (SRC == 1) ? g_bufA : g_bufB;

    int warp = (blockIdx.x * blockDim.x + threadIdx.x) >> 5;
    int lane = threadIdx.x & 31;
    if (warp >= n) return;

    int start = g_off[warp];
    int end   = g_off[warp + 1];
    float dr  = g_dinv[warp];            // broadcast load

    float4 acc = make_float4(0.f, 0.f, 0.f, 0.f);

    for (int base = start; base < end; base += 32) {
        int idx = base + lane;
        int c = 0;
        if (idx < end) c = __ldcs(&g_col[idx]);   // streaming: protect Hs in L2
        int cnt = end - base;
        if (cnt > 32) cnt = 32;
        #pragma unroll 8
        for (int j = 0; j < cnt; ++j) {
            int cj = __shfl_sync(0xffffffffu, c, j);
            uint2 hv = __ldg(((const uint2*)(Hin + (size_t)cj * FEAT)) + lane);
            float2 f01 = __half22float2(*reinterpret_cast<__half2*>(&hv.x));
            float2 f23 = __half22float2(*reinterpret_cast<__half2*>(&hv.y));
            acc.x += f01.x;
            acc.y += f01.y;
            acc.z += f23.x;
            acc.w += f23.y;
        }
    }

    if (DST == 0) {
        // final hop: H3 = dinv_r * S
        acc.x *= dr; acc.y *= dr; acc.z *= dr; acc.w *= dr;
        ((float4*)(Oext + (size_t)warp * FEAT))[lane] = acc;
    } else {
        // intermediate hop: Hs' = dinv_r^2 * S
        float s = dr * dr;
        __half* Hout = (DST == 1) ? g_bufA : g_bufB;
        __half2 o0 = __floats2half2_rn(acc.x * s, acc.y * s);
        __half2 o1 = __floats2half2_rn(acc.z * s, acc.w * s);
        uint2 o;
        o.x = *reinterpret_cast<unsigned int*>(&o0);
        o.y = *reinterpret_cast<unsigned int*>(&o1);
        ((uint2*)(Hout + (size_t)warp * FEAT))[lane] = o;
    }
}

// ---------------------------------------------------------------------------
extern "C" void kernel_launch(void* const* d_in, const int* in_sizes, int n_in,
                              void* d_out, int out_size) {
    const float* h_local = (const float*)d_in[0];
    const void*  edges   = d_in[1];

    int n = in_sizes[0] / FEAT;     // number of nodes (100000)
    int e = in_sizes[1] / 2;        // number of edges (3200000)

    const int T = 256;
    int nb_n    = (n + T - 1) / T;
    int eh      = (e + 1) / 2;                       // edge pairs
    int nb_e2   = (eh + T - 1) / T;
    int nb_f    = (eh + n + T - 1) / T;
    int nscan   = (n + SCAN_B - 1) / SCAN_B;         // 98 scan blocks
    int total4  = n * FEAT / 4;
    int nb_cvt  = (total4 + SCAN_B - 1) / SCAN_B;    // cvt blocks

    // --- CSR build: init -> hist -> single-pass scan (+cvt) -> fill ---
    k_deg_init<<<nb_n, T>>>((const unsigned int*)edges, n, nscan);
    k_deg_hist<<<nb_e2, T>>>(edges, e);
    k_scan<<<nscan + nb_cvt, SCAN_B>>>(h_local, n, e + n, nscan, total4);
    k_fill<<<nb_f, T>>>(edges, e, n);

    // --- 3 propagation hops: A -> B -> A -> f32 out ---
    int warps_per_block = T / 32;
    int nb_spmm = (n + warps_per_block - 1) / warps_per_block;
    k_spmm<1, 2><<<nb_spmm, T>>>(nullptr, n);
    k_spmm<2, 1><<<nb_spmm, T>>>(nullptr, n);
    k_spmm<1, 0><<<nb_spmm, T>>>((float*)d_out, n);
}